// round 11
// baseline (speedup 1.0000x reference)
#include <cuda_runtime.h>
#include <cuda_fp16.h>
#include <math.h>
#include <stdint.h>

#define BB 4
#define TT 2048
#define CC 1024
#define HH 16
#define HD 64
#define MT (BB*TT)   // 8192
#define QS (3*CC)    // fused QKV row stride = 3072

// ---- scratch (static device arrays; no allocation allowed) ----
__device__ __half g_x16[MT*CC];
__device__ __half g_w16[4*CC*CC];     // Wq,Wk,Wv packed + Wo
__device__ float  g_bqkv[QS];
__device__ __half g_qkv16[(size_t)MT*QS];
__device__ __half g_y16[MT*CC];

// ============================================================
// PTX helpers
// ============================================================
__device__ __forceinline__ uint32_t smem_u32(const void* p) {
    uint32_t a;
    asm("{ .reg .u64 t; cvta.to.shared.u64 t, %1; cvt.u32.u64 %0, t; }" : "=r"(a) : "l"(p));
    return a;
}
#define CP16(dst, src) \
    asm volatile("cp.async.cg.shared.global [%0], [%1], 16;" :: "r"(dst), "l"(src))
#define CP_COMMIT() asm volatile("cp.async.commit_group;" ::: "memory")
#define CP_WAIT0()  asm volatile("cp.async.wait_group 0;" ::: "memory")
#define CP_WAIT2()  asm volatile("cp.async.wait_group 2;" ::: "memory")
#define LDSM4(r0, r1, r2, r3, addr) \
    asm volatile("ldmatrix.sync.aligned.m8n8.x4.shared.b16 {%0,%1,%2,%3}, [%4];" \
                 : "=r"(r0), "=r"(r1), "=r"(r2), "=r"(r3) : "r"(addr))
#define LDSM4T(r0, r1, r2, r3, addr) \
    asm volatile("ldmatrix.sync.aligned.m8n8.x4.trans.shared.b16 {%0,%1,%2,%3}, [%4];" \
                 : "=r"(r0), "=r"(r1), "=r"(r2), "=r"(r3) : "r"(addr))
#define MMA16816(d, a, b0, b1) \
    asm volatile("mma.sync.aligned.m16n8k16.row.col.f32.f16.f16.f32 " \
                 "{%0,%1,%2,%3}, {%4,%5,%6,%7}, {%8,%9}, {%0,%1,%2,%3};" \
                 : "+f"((d)[0]), "+f"((d)[1]), "+f"((d)[2]), "+f"((d)[3]) \
                 : "r"((a)[0]), "r"((a)[1]), "r"((a)[2]), "r"((a)[3]), \
                   "r"(b0), "r"(b1))

// exp2 of two fp32 args -> packed fp16x2 (lo, hi)
__device__ __forceinline__ uint32_t exp2_pair(float lo, float hi) {
    uint32_t h, d;
    asm("cvt.rn.f16x2.f32 %0, %1, %2;" : "=r"(h) : "f"(hi), "f"(lo));
    asm("ex2.approx.f16x2 %0, %1;" : "=r"(d) : "r"(h));
    return d;
}

// ============================================================
// Fused fp32 -> fp16 convert: x (MT*CC) + 4 weights (CC*CC each)
// ============================================================
#define N4X (MT*CC/4)       // 2097152
#define N4W (CC*CC/4)       // 262144
#define N4TOT (N4X + 4*N4W) // 3145728

__global__ __launch_bounds__(256) void cvt_all(
    const float4* __restrict__ x,
    const float4* __restrict__ w0, const float4* __restrict__ w1,
    const float4* __restrict__ w2, const float4* __restrict__ w3,
    __half2* __restrict__ xd, __half2* __restrict__ wd)
{
    const int stride = gridDim.x * blockDim.x;
    for (int i = blockIdx.x * blockDim.x + threadIdx.x; i < N4TOT; i += stride) {
        const float4* s; __half2* d; int off;
        if (i < N4X) { s = x; d = xd; off = i; }
        else {
            int j = i - N4X;
            int rg = j >> 18;                 // N4W = 2^18
            off = j & (N4W - 1);
            s = (rg == 0) ? w0 : (rg == 1) ? w1 : (rg == 2) ? w2 : w3;
            d = wd + (size_t)rg * (2 * N4W);
        }
        float4 v = s[off];
        d[2*off]   = __floats2half2_rn(v.x, v.y);
        d[2*off+1] = __floats2half2_rn(v.z, v.w);
    }
}

__global__ void pack_bias(const float* __restrict__ bq, const float* __restrict__ bk,
                          const float* __restrict__ bv, float* __restrict__ o)
{
    int i = blockIdx.x * blockDim.x + threadIdx.x;   // 0..3071
    const float* src = (i < CC) ? bq : (i < 2*CC) ? bk : bv;
    o[i] = src[i & (CC - 1)];
}

// ============================================================
// HMMA GEMM: Y[m,n] = sum_k A[m,k]*B[n,k] + bias[n]
// BM=128 BN=128 BK=32, 4 warps (2x2), warp tile 64x64, m16n8k16.
// 4-stage cp.async ring, ONE barrier per iteration, wait_group 2.
// ============================================================
#define GBM 128
#define GBN 128
#define GBK 32
#define NKIT (CC/GBK)        // 32
#define A_B 8192             // 128x32 fp16
#define B_B 8192
#define STG_B (A_B + B_B)    // 16384
#define NSTG 4
#define GSMEM (NSTG*STG_B)   // 65536

__device__ __forceinline__ void ld_stage(
    uint32_t sbase, int stage,
    const __half* __restrict__ A, const __half* __restrict__ B,
    int m0, int n0, int k0, int tid)
{
    uint32_t st = sbase + stage * STG_B;
    #pragma unroll
    for (int t = 0; t < 4; t++) {        // 512 chunks each for A and B
        int i = tid + t * 128;
        int r = i >> 2, c = i & 3;
        uint32_t soff = ((uint32_t)(r * 4 + (c ^ (r & 3)))) << 4;
        CP16(st + soff,       A + (size_t)(m0 + r) * CC + k0 + c * 8);
        CP16(st + A_B + soff, B + (size_t)(n0 + r) * CC + k0 + c * 8);
    }
}

template <typename OutT>
__global__ __launch_bounds__(128, 2) void gemm_mma(
    const __half* __restrict__ A, const __half* __restrict__ B,
    const float* __restrict__ bias, OutT* __restrict__ Y, int ldc)
{
    extern __shared__ char smem[];
    const uint32_t sbase = smem_u32(smem);
    const int tid = threadIdx.x, wid = tid >> 5, lid = tid & 31;
    const int m0 = blockIdx.y * GBM, n0 = blockIdx.x * GBN;
    const int wm = wid >> 1, wn = wid & 1;     // 2x2 warp grid, tile 64x64

    float acc[4][8][4];
    #pragma unroll
    for (int a = 0; a < 4; a++)
        #pragma unroll
        for (int b = 0; b < 8; b++)
            #pragma unroll
            for (int c = 0; c < 4; c++) acc[a][b][c] = 0.f;

    ld_stage(sbase, 0, A, B, m0, n0, 0, tid);       CP_COMMIT();
    ld_stage(sbase, 1, A, B, m0, n0, GBK, tid);     CP_COMMIT();
    ld_stage(sbase, 2, A, B, m0, n0, 2 * GBK, tid); CP_COMMIT();

    const int a_r = wm * 64 + (lid & 15);
    const int a_c = lid >> 4;
    const int b_r = wn * 64 + (lid & 7) + ((lid >> 4) << 3);
    const int b_c = (lid & 15) >> 3;

    for (int kb = 0; kb < NKIT; kb++) {
        CP_WAIT2();
        __syncthreads();
        const uint32_t st = sbase + (kb & 3) * STG_B;

        #pragma unroll
        for (int kk = 0; kk < 2; kk++) {
            uint32_t af[4][4], bf[4][4];
            #pragma unroll
            for (int mi = 0; mi < 4; mi++) {
                int r = a_r + mi * 16;
                int c16 = kk * 2 + a_c;
                uint32_t off = ((uint32_t)(r * 4 + (c16 ^ (r & 3)))) << 4;
                LDSM4(af[mi][0], af[mi][1], af[mi][2], af[mi][3], st + off);
            }
            #pragma unroll
            for (int nj = 0; nj < 4; nj++) {
                int r = b_r + nj * 16;
                int c16 = kk * 2 + b_c;
                uint32_t off = ((uint32_t)(r * 4 + (c16 ^ (r & 3)))) << 4;
                LDSM4(bf[nj][0], bf[nj][1], bf[nj][2], bf[nj][3], st + A_B + off);
            }
            #pragma unroll
            for (int mi = 0; mi < 4; mi++)
                #pragma unroll
                for (int nj = 0; nj < 4; nj++) {
                    MMA16816(acc[mi][nj * 2],     af[mi], bf[nj][0], bf[nj][1]);
                    MMA16816(acc[mi][nj * 2 + 1], af[mi], bf[nj][2], bf[nj][3]);
                }
        }
        if (kb + 3 < NKIT)
            ld_stage(sbase, (kb + 3) & 3, A, B, m0, n0, (kb + 3) * GBK, tid);
        CP_COMMIT();
    }

    #pragma unroll
    for (int mi = 0; mi < 4; mi++) {
        #pragma unroll
        for (int nj = 0; nj < 8; nj++) {
            int row = m0 + wm * 64 + mi * 16 + (lid >> 2);
            int col = n0 + wn * 64 + nj * 8 + (lid & 3) * 2;
            float b0 = __ldg(bias + col), b1 = __ldg(bias + col + 1);
            float v00 = acc[mi][nj][0] + b0, v01 = acc[mi][nj][1] + b1;
            float v10 = acc[mi][nj][2] + b0, v11 = acc[mi][nj][3] + b1;
            if (sizeof(OutT) == 2) {
                *(__half2*)((__half*)Y + (size_t)row * ldc + col)       = __floats2half2_rn(v00, v01);
                *(__half2*)((__half*)Y + (size_t)(row + 8) * ldc + col) = __floats2half2_rn(v10, v11);
            } else {
                *(float2*)((float*)Y + (size_t)row * ldc + col)       = make_float2(v00, v01);
                *(float2*)((float*)Y + (size_t)(row + 8) * ldc + col) = make_float2(v10, v11);
            }
        }
    }
}

// ============================================================
// Flash attention (causal), fp16 HMMA, base-2 softmax, KEY-SPLIT:
// AQ=64 queries/CTA; 8 warps; warp pair (2j,2j+1) shares q rows
// [16j,16j+16) — warp 2j handles keys [0,32) of each tile, warp 2j+1
// keys [32,64). Private (m,l,acc) per warp; one smem merge at end.
// m init = MINIT = -1e4 (NOT -1e30): keeps mn bounded so fully-masked
// tiles give P==0 exactly (no fmul/fma rounding-residual inf).
// 4-slot KV rings, one barrier/tile, wait_group 2.
// smem: Q [0,8K) | K slots [8K,40K) | V slots [40K,72K); merge reuses [8K,..)
// ============================================================
#define AQ 64
#define AK 64
#define ONES16 0x3C003C00u
#define MINIT (-1e4f)
#define ASM_K 8192
#define ASM_V 40960
#define ASMEM 73728

__global__ __launch_bounds__(256, 2) void attn_mma(
    const __half* __restrict__ QKV, __half* __restrict__ Y)
{
    extern __shared__ char sm[];
    const uint32_t sb = smem_u32(sm);

    const int tid = threadIdx.x, wid = tid >> 5, lid = tid & 31;
    const int qpair = wid >> 1;           // 0..3: q-row group
    const int half  = wid & 1;            // key half of every tile
    const int bh = blockIdx.y;
    const int b  = bh / HH;
    const int h  = bh % HH;
    const int qt = gridDim.x - 1 - blockIdx.x;   // long blocks first
    const int t0 = qt * AQ;
    const int nkv = qt + 1;               // 64-key tiles

    const size_t headoff = (size_t)b * TT * QS + (size_t)h * HD;
    const __half* Qg = QKV + headoff + (size_t)t0 * QS;

    // ---- G0: Q tile (64x64) ----
    #pragma unroll
    for (int i = 0; i < 2; i++) {
        int idx = tid + i * 256;          // 0..511
        int r = idx >> 3, ch = idx & 7;
        uint32_t soff = (uint32_t)(r * 128 + ((ch ^ (r & 7)) << 4));
        CP16(sb + soff, Qg + (size_t)r * QS + ch * 8);
    }
    CP_COMMIT();

    auto ld_kv = [&](int slot, int kb) {
        const __half* Kg = QKV + CC   + headoff + (size_t)(kb * AK) * QS;
        const __half* Vg = QKV + 2*CC + headoff + (size_t)(kb * AK) * QS;
        uint32_t kb32 = sb + ASM_K + slot * 8192;
        uint32_t vb32 = sb + ASM_V + slot * 8192;
        #pragma unroll
        for (int i = 0; i < 2; i++) {
            int idx = tid + i * 256;      // 0..511
            int r = idx >> 3, ch = idx & 7;
            uint32_t soff = (uint32_t)(r * 128 + ((ch ^ (r & 7)) << 4));
            CP16(kb32 + soff, Kg + (size_t)r * QS + ch * 8);
            CP16(vb32 + soff, Vg + (size_t)r * QS + ch * 8);
        }
    };

    // prologue: G1=kv0, G2=kv1, G3=kv2 (guards; commit regardless)
    ld_kv(0, 0);                 CP_COMMIT();
    if (nkv > 1) ld_kv(1, 1);    CP_COMMIT();
    if (nkv > 2) ld_kv(2, 2);    CP_COMMIT();

    uint32_t qf[4][4];
    float acc[8][4];
    #pragma unroll
    for (int n = 0; n < 8; n++)
        #pragma unroll
        for (int c = 0; c < 4; c++) acc[n][c] = 0.f;
    float m0 = MINIT, m1 = MINIT, l0 = 0.f, l1 = 0.f;
    const float cl = 0.04508422f;         // log2(e)/32

    const int g = lid >> 2;
    const int tg = lid & 3;
    const int qg0 = t0 + qpair * 16 + g;  // global query row (row0)
    const int t8 = lid >> 3;

    for (int kb = 0; kb < nkv; kb++) {
        CP_WAIT2();
        __syncthreads();   // frees KV slot (kb-1)%4

        if (kb == 0) {
            #pragma unroll
            for (int kk = 0; kk < 4; kk++) {
                int row = qpair * 16 + (lid & 7) + ((lid >> 3) & 1) * 8;
                int ch  = 2 * kk + (lid >> 4);
                uint32_t addr = sb + (uint32_t)(row * 128 + ((ch ^ (row & 7)) << 4));
                LDSM4(qf[kk][0], qf[kk][1], qf[kk][2], qf[kk][3], addr);
            }
        }

        const uint32_t kbase = sb + ASM_K + (kb & 3) * 8192;
        const uint32_t vbase = sb + ASM_V + (kb & 3) * 8192;

        // ---- S = Q K^T over this warp's 32-key half ----
        float s[4][4];
        #pragma unroll
        for (int j = 0; j < 4; j++)
            #pragma unroll
            for (int c = 0; c < 4; c++) s[j][c] = 0.f;

        #pragma unroll
        for (int kk = 0; kk < 4; kk++) {
            #pragma unroll
            for (int jp = 0; jp < 2; jp++) {
                int j = 2 * jp + (t8 >> 1);
                int ch = 2 * kk + (t8 & 1);
                int keyrow = 32 * half + 8 * j + (lid & 7);
                uint32_t addr = kbase + (uint32_t)(keyrow * 128 + ((ch ^ (keyrow & 7)) << 4));
                uint32_t f0, f1, f2, f3;
                LDSM4(f0, f1, f2, f3, addr);
                MMA16816(s[2 * jp],     qf[kk], f0, f1);
                MMA16816(s[2 * jp + 1], qf[kk], f2, f3);
            }
        }

        if (kb == nkv - 1) {     // AQ==AK: only diagonal tile needs mask
            #pragma unroll
            for (int j = 0; j < 4; j++) {
                int kc = kb * AK + 32 * half + 8 * j + tg * 2;
                if (kc     > qg0)     s[j][0] = -1e30f;
                if (kc + 1 > qg0)     s[j][1] = -1e30f;
                if (kc     > qg0 + 8) s[j][2] = -1e30f;
                if (kc + 1 > qg0 + 8) s[j][3] = -1e30f;
            }
        }

        // ---- row max ----
        float tm0 = -1e30f, tm1 = -1e30f;
        #pragma unroll
        for (int j = 0; j < 4; j++) {
            tm0 = fmaxf(tm0, fmaxf(s[j][0], s[j][1]));
            tm1 = fmaxf(tm1, fmaxf(s[j][2], s[j][3]));
        }
        tm0 = fmaxf(tm0, __shfl_xor_sync(0xffffffffu, tm0, 1));
        tm0 = fmaxf(tm0, __shfl_xor_sync(0xffffffffu, tm0, 2));
        tm1 = fmaxf(tm1, __shfl_xor_sync(0xffffffffu, tm1, 1));
        tm1 = fmaxf(tm1, __shfl_xor_sync(0xffffffffu, tm1, 2));

        // m0,m1 >= MINIT always, so mn stays >= MINIT: fully-masked tiles
        // give fmaf(s,cl,-mn) = -4.5e28 -> fp16 -inf -> P = 0 exactly.
        float mn0 = fmaxf(m0, tm0 * cl), mn1 = fmaxf(m1, tm1 * cl);
        float cr0 = exp2f(m0 - mn0), cr1 = exp2f(m1 - mn1);
        m0 = mn0; m1 = mn1;

        // ---- P = 2^(s*cl - m) into packed fp16 fragments ----
        uint32_t ap[2][4];
        #pragma unroll
        for (int kk = 0; kk < 2; kk++) {
            ap[kk][0] = exp2_pair(fmaf(s[2*kk][0],   cl, -mn0), fmaf(s[2*kk][1],   cl, -mn0));
            ap[kk][1] = exp2_pair(fmaf(s[2*kk][2],   cl, -mn1), fmaf(s[2*kk][3],   cl, -mn1));
            ap[kk][2] = exp2_pair(fmaf(s[2*kk+1][0], cl, -mn0), fmaf(s[2*kk+1][1], cl, -mn0));
            ap[kk][3] = exp2_pair(fmaf(s[2*kk+1][2], cl, -mn1), fmaf(s[2*kk+1][3], cl, -mn1));
        }

        // ---- row sums via P @ ones ----
        float ld[4] = {0.f, 0.f, 0.f, 0.f};
        #pragma unroll
        for (int kk = 0; kk < 2; kk++)
            MMA16816(ld, ap[kk], ONES16, ONES16);
        l0 = l0 * cr0 + ld[0];
        l1 = l1 * cr1 + ld[2];

        #pragma unroll
        for (int n = 0; n < 8; n++) {
            acc[n][0] *= cr0; acc[n][1] *= cr0;
            acc[n][2] *= cr1; acc[n][3] *= cr1;
        }

        // ---- acc += P V (this warp's 32 key rows) ----
        #pragma unroll
        for (int kk = 0; kk < 2; kk++) {
            #pragma unroll
            for (int np = 0; np < 4; np++) {
                int n = 2 * np + (t8 >> 1);
                int keyrow = 32 * half + 16 * kk + (t8 & 1) * 8 + (lid & 7);
                uint32_t addr = vbase + (uint32_t)(keyrow * 128 + ((n ^ (keyrow & 7)) << 4));
                uint32_t f0, f1, f2, f3;
                LDSM4T(f0, f1, f2, f3, addr);
                MMA16816(acc[2 * np],     ap[kk], f0, f1);
                MMA16816(acc[2 * np + 1], ap[kk], f2, f3);
            }
        }

        if (kb + 3 < nkv) ld_kv((kb + 3) & 3, kb + 3);
        CP_COMMIT();
    }

    // ---- merge warp pairs (odd half -> smem, even half combines) ----
    CP_WAIT0();
    __syncthreads();
    float* mbuf = (float*)(sm + ASM_K) + qpair * (32 * 40) + lid * 40;
    if (half == 1) {
        #pragma unroll
        for (int n = 0; n < 8; n++) {
            mbuf[4*n]   = acc[n][0]; mbuf[4*n+1] = acc[n][1];
            mbuf[4*n+2] = acc[n][2]; mbuf[4*n+3] = acc[n][3];
        }
        mbuf[32] = m0; mbuf[33] = m1; mbuf[34] = l0; mbuf[35] = l1;
    }
    __syncthreads();
    if (half == 0) {
        float pm0 = mbuf[32], pm1 = mbuf[33], pl0 = mbuf[34], pl1 = mbuf[35];
        float M0 = fmaxf(m0, pm0), M1 = fmaxf(m1, pm1);
        float f0 = exp2f(m0 - M0), p0 = exp2f(pm0 - M0);
        float f1 = exp2f(m1 - M1), p1 = exp2f(pm1 - M1);
        float inv0 = 1.f / (l0 * f0 + pl0 * p0);
        float inv1 = 1.f / (l1 * f1 + pl1 * p1);

        const size_t yoff = (size_t)b * TT * CC + (size_t)h * HD;
        __half* Y0 = Y + yoff + (size_t)(qg0) * CC + tg * 2;
        __half* Y1 = Y0 + 8 * CC;
        #pragma unroll
        for (int n = 0; n < 8; n++) {
            float v0 = (acc[n][0] * f0 + mbuf[4*n]   * p0) * inv0;
            float v1 = (acc[n][1] * f0 + mbuf[4*n+1] * p0) * inv0;
            float v2 = (acc[n][2] * f1 + mbuf[4*n+2] * p1) * inv1;
            float v3 = (acc[n][3] * f1 + mbuf[4*n+3] * p1) * inv1;
            *(__half2*)(Y0 + n * 8) = __floats2half2_rn(v0, v1);
            *(__half2*)(Y1 + n * 8) = __floats2half2_rn(v2, v3);
        }
    }
}

// ============================================================
extern "C" void kernel_launch(void* const* d_in, const int* in_sizes, int n_in,
                              void* d_out, int out_size) {
    const float* x  = (const float*)d_in[0];
    const float* Wq = (const float*)d_in[1];
    const float* bq = (const float*)d_in[2];
    const float* Wk = (const float*)d_in[3];
    const float* bk = (const float*)d_in[4];
    const float* Wv = (const float*)d_in[5];
    const float* bv = (const float*)d_in[6];
    const float* Wo = (const float*)d_in[7];
    const float* bo = (const float*)d_in[8];

    __half *x16, *w16, *qkv16, *y16;
    float *bqkv;
    cudaGetSymbolAddress((void**)&x16,   g_x16);
    cudaGetSymbolAddress((void**)&w16,   g_w16);
    cudaGetSymbolAddress((void**)&qkv16, g_qkv16);
    cudaGetSymbolAddress((void**)&y16,   g_y16);
    cudaGetSymbolAddress((void**)&bqkv,  g_bqkv);

    cudaFuncSetAttribute(gemm_mma<__half>, cudaFuncAttributeMaxDynamicSharedMemorySize, GSMEM);
    cudaFuncSetAttribute(gemm_mma<float>,  cudaFuncAttributeMaxDynamicSharedMemorySize, GSMEM);
    cudaFuncSetAttribute(attn_mma,         cudaFuncAttributeMaxDynamicSharedMemorySize, ASMEM);

    cvt_all<<<3072, 256>>>((const float4*)x, (const float4*)Wq, (const float4*)Wk,
                           (const float4*)Wv, (const float4*)Wo,
                           (__half2*)x16, (__half2*)w16);
    pack_bias<<<QS / 256, 256>>>(bq, bk, bv, bqkv);

    dim3 gqkv(QS / GBN, MT / GBM);   // (24, 64)
    gemm_mma<__half><<<gqkv, 128, GSMEM>>>(x16, w16, bqkv, qkv16, QS);

    dim3 ag(TT / AQ, BB * HH);       // (32, 64)
    attn_mma<<<ag, 256, ASMEM>>>(qkv16, y16);

    dim3 go(CC / GBN, MT / GBM);     // (8, 64)
    gemm_mma<float><<<go, 128, GSMEM>>>(y16, w16 + 3*CC*CC, bo, (float*)d_out, CC);
}

// round 12
// speedup vs baseline: 1.1152x; 1.1152x over previous
#include <cuda_runtime.h>
#include <cuda_fp16.h>
#include <math.h>
#include <stdint.h>

#define BB 4
#define TT 2048
#define CC 1024
#define HH 16
#define HD 64
#define MT (BB*TT)   // 8192
#define QS (3*CC)    // fused QKV row stride = 3072

// ---- scratch (static device arrays; no allocation allowed) ----
__device__ __half g_x16[MT*CC];
__device__ __half g_w16[4*CC*CC];     // Wq,Wk,Wv packed + Wo
__device__ float  g_bqkv[QS];
__device__ __half g_qkv16[(size_t)MT*QS];
__device__ __half g_y16[MT*CC];

// ============================================================
// PTX helpers
// ============================================================
__device__ __forceinline__ uint32_t smem_u32(const void* p) {
    uint32_t a;
    asm("{ .reg .u64 t; cvta.to.shared.u64 t, %1; cvt.u32.u64 %0, t; }" : "=r"(a) : "l"(p));
    return a;
}
#define CP16(dst, src) \
    asm volatile("cp.async.cg.shared.global [%0], [%1], 16;" :: "r"(dst), "l"(src))
#define CP_COMMIT() asm volatile("cp.async.commit_group;" ::: "memory")
#define CP_WAIT0()  asm volatile("cp.async.wait_group 0;" ::: "memory")
#define CP_WAIT1()  asm volatile("cp.async.wait_group 1;" ::: "memory")
#define CP_WAIT2()  asm volatile("cp.async.wait_group 2;" ::: "memory")
#define LDSM4(r0, r1, r2, r3, addr) \
    asm volatile("ldmatrix.sync.aligned.m8n8.x4.shared.b16 {%0,%1,%2,%3}, [%4];" \
                 : "=r"(r0), "=r"(r1), "=r"(r2), "=r"(r3) : "r"(addr))
#define LDSM4T(r0, r1, r2, r3, addr) \
    asm volatile("ldmatrix.sync.aligned.m8n8.x4.trans.shared.b16 {%0,%1,%2,%3}, [%4];" \
                 : "=r"(r0), "=r"(r1), "=r"(r2), "=r"(r3) : "r"(addr))
#define MMA16816(d, a, b0, b1) \
    asm volatile("mma.sync.aligned.m16n8k16.row.col.f32.f16.f16.f32 " \
                 "{%0,%1,%2,%3}, {%4,%5,%6,%7}, {%8,%9}, {%0,%1,%2,%3};" \
                 : "+f"((d)[0]), "+f"((d)[1]), "+f"((d)[2]), "+f"((d)[3]) \
                 : "r"((a)[0]), "r"((a)[1]), "r"((a)[2]), "r"((a)[3]), \
                   "r"(b0), "r"(b1))

// exp2 of two fp32 args -> packed fp16x2 (lo, hi)
__device__ __forceinline__ uint32_t exp2_pair(float lo, float hi) {
    uint32_t h, d;
    asm("cvt.rn.f16x2.f32 %0, %1, %2;" : "=r"(h) : "f"(hi), "f"(lo));
    asm("ex2.approx.f16x2 %0, %1;" : "=r"(d) : "r"(h));
    return d;
}

// ============================================================
// Fused fp32 -> fp16 convert: x (MT*CC) + 4 weights (CC*CC each)
// ============================================================
#define N4X (MT*CC/4)       // 2097152
#define N4W (CC*CC/4)       // 262144
#define N4TOT (N4X + 4*N4W) // 3145728

__global__ __launch_bounds__(256) void cvt_all(
    const float4* __restrict__ x,
    const float4* __restrict__ w0, const float4* __restrict__ w1,
    const float4* __restrict__ w2, const float4* __restrict__ w3,
    __half2* __restrict__ xd, __half2* __restrict__ wd)
{
    const int stride = gridDim.x * blockDim.x;
    for (int i = blockIdx.x * blockDim.x + threadIdx.x; i < N4TOT; i += stride) {
        const float4* s; __half2* d; int off;
        if (i < N4X) { s = x; d = xd; off = i; }
        else {
            int j = i - N4X;
            int rg = j >> 18;                 // N4W = 2^18
            off = j & (N4W - 1);
            s = (rg == 0) ? w0 : (rg == 1) ? w1 : (rg == 2) ? w2 : w3;
            d = wd + (size_t)rg * (2 * N4W);
        }
        float4 v = s[off];
        d[2*off]   = __floats2half2_rn(v.x, v.y);
        d[2*off+1] = __floats2half2_rn(v.z, v.w);
    }
}

__global__ void pack_bias(const float* __restrict__ bq, const float* __restrict__ bk,
                          const float* __restrict__ bv, float* __restrict__ o)
{
    int i = blockIdx.x * blockDim.x + threadIdx.x;   // 0..3071
    const float* src = (i < CC) ? bq : (i < 2*CC) ? bk : bv;
    o[i] = src[i & (CC - 1)];
}

// ============================================================
// HMMA GEMM: Y[m,n] = sum_k A[m,k]*B[n,k] + bias[n]
// BM=128 BN=128 BK=64, 4 warps (2x2), warp tile 64x64, m16n8k16.
// 3-stage cp.async ring (32KB/stage), ONE barrier per iteration,
// wait_group 1, 2 CTAs/SM. Swizzle c^(r&7) on 128B rows.
// ============================================================
#define GBM 128
#define GBN 128
#define GBK 64
#define NKIT (CC/GBK)        // 16
#define A_B 16384            // 128x64 fp16
#define B_B 16384
#define STG_B (A_B + B_B)    // 32768
#define NSTG 3
#define GSMEM (NSTG*STG_B)   // 98304

__device__ __forceinline__ void ld_stage(
    uint32_t sbase, int stage,
    const __half* __restrict__ A, const __half* __restrict__ B,
    int m0, int n0, int k0, int tid)
{
    uint32_t st = sbase + stage * STG_B;
    #pragma unroll
    for (int t = 0; t < 8; t++) {        // 1024 16B chunks each for A and B
        int i = tid + t * 128;
        int r = i >> 3, c = i & 7;
        uint32_t soff = ((uint32_t)(r * 8 + (c ^ (r & 7)))) << 4;
        CP16(st + soff,       A + (size_t)(m0 + r) * CC + k0 + c * 8);
        CP16(st + A_B + soff, B + (size_t)(n0 + r) * CC + k0 + c * 8);
    }
}

template <typename OutT>
__global__ __launch_bounds__(128, 2) void gemm_mma(
    const __half* __restrict__ A, const __half* __restrict__ B,
    const float* __restrict__ bias, OutT* __restrict__ Y, int ldc)
{
    extern __shared__ char smem[];
    const uint32_t sbase = smem_u32(smem);
    const int tid = threadIdx.x, wid = tid >> 5, lid = tid & 31;
    const int m0 = blockIdx.y * GBM, n0 = blockIdx.x * GBN;
    const int wm = wid >> 1, wn = wid & 1;     // 2x2 warp grid, tile 64x64

    float acc[4][8][4];
    #pragma unroll
    for (int a = 0; a < 4; a++)
        #pragma unroll
        for (int b = 0; b < 8; b++)
            #pragma unroll
            for (int c = 0; c < 4; c++) acc[a][b][c] = 0.f;

    // prologue: stages 0,1 -> groups G0,G1
    ld_stage(sbase, 0, A, B, m0, n0, 0, tid);   CP_COMMIT();
    ld_stage(sbase, 1, A, B, m0, n0, GBK, tid); CP_COMMIT();

    const int a_r = wm * 64 + (lid & 15);
    const int a_c = lid >> 4;
    const int b_r = wn * 64 + (lid & 7) + ((lid >> 4) << 3);
    const int b_c = (lid & 15) >> 3;

    for (int kb = 0; kb < NKIT; kb++) {
        // need G_kb; exactly 1 newer group committed -> wait 1
        CP_WAIT1();
        __syncthreads();   // frees slot (kb-1)%3 (consumed last iter)
        const uint32_t st = sbase + (kb % 3) * STG_B;

        #pragma unroll
        for (int kk = 0; kk < 4; kk++) {
            uint32_t af[4][4], bf[4][4];
            #pragma unroll
            for (int mi = 0; mi < 4; mi++) {
                int r = a_r + mi * 16;
                int c16 = kk * 2 + a_c;
                uint32_t off = ((uint32_t)(r * 8 + (c16 ^ (r & 7)))) << 4;
                LDSM4(af[mi][0], af[mi][1], af[mi][2], af[mi][3], st + off);
            }
            #pragma unroll
            for (int nj = 0; nj < 4; nj++) {
                int r = b_r + nj * 16;
                int c16 = kk * 2 + b_c;
                uint32_t off = ((uint32_t)(r * 8 + (c16 ^ (r & 7)))) << 4;
                LDSM4(bf[nj][0], bf[nj][1], bf[nj][2], bf[nj][3], st + A_B + off);
            }
            #pragma unroll
            for (int mi = 0; mi < 4; mi++)
                #pragma unroll
                for (int nj = 0; nj < 4; nj++) {
                    MMA16816(acc[mi][nj * 2],     af[mi], bf[nj][0], bf[nj][1]);
                    MMA16816(acc[mi][nj * 2 + 1], af[mi], bf[nj][2], bf[nj][3]);
                }
        }
        // prefetch kb+2 into slot (kb+2)%3 == (kb-1)%3 (freed by this iter's sync)
        if (kb + 2 < NKIT)
            ld_stage(sbase, (kb + 2) % 3, A, B, m0, n0, (kb + 2) * GBK, tid);
        CP_COMMIT();   // always commit to keep group count uniform
    }

    #pragma unroll
    for (int mi = 0; mi < 4; mi++) {
        #pragma unroll
        for (int nj = 0; nj < 8; nj++) {
            int row = m0 + wm * 64 + mi * 16 + (lid >> 2);
            int col = n0 + wn * 64 + nj * 8 + (lid & 3) * 2;
            float b0 = __ldg(bias + col), b1 = __ldg(bias + col + 1);
            float v00 = acc[mi][nj][0] + b0, v01 = acc[mi][nj][1] + b1;
            float v10 = acc[mi][nj][2] + b0, v11 = acc[mi][nj][3] + b1;
            if (sizeof(OutT) == 2) {
                *(__half2*)((__half*)Y + (size_t)row * ldc + col)       = __floats2half2_rn(v00, v01);
                *(__half2*)((__half*)Y + (size_t)(row + 8) * ldc + col) = __floats2half2_rn(v10, v11);
            } else {
                *(float2*)((float*)Y + (size_t)row * ldc + col)       = make_float2(v00, v01);
                *(float2*)((float*)Y + (size_t)(row + 8) * ldc + col) = make_float2(v10, v11);
            }
        }
    }
}

// ============================================================
// Flash attention (causal), m16n8k16 fp16 HMMA, base-2 softmax.
// (R9 version — best known: 130 us.)
// AQ=128 queries/CTA (8 warps x 16 rows), AK=64 keys/tile.
// 4-slot K and V cp.async rings, ONE barrier per tile, wait_group 2.
// smem: Q [0,16K) | K slots [16K,48K) | V slots [48K,80K)  (dynamic 80KB)
// ============================================================
#define AQ 128
#define AK 64
#define ONES16 0x3C003C00u
#define ASM_K 16384
#define ASM_V 49152
#define ASMEM 81920

__global__ __launch_bounds__(256, 2) void attn_mma(
    const __half* __restrict__ QKV, __half* __restrict__ Y)
{
    extern __shared__ char sm[];
    const uint32_t sb = smem_u32(sm);

    const int tid = threadIdx.x, wid = tid >> 5, lid = tid & 31;
    const int bh = blockIdx.y;
    const int b  = bh / HH;
    const int h  = bh % HH;
    const int qt = gridDim.x - 1 - blockIdx.x;   // long blocks first
    const int t0 = qt * AQ;
    const int nkv = 2 * qt + 2;                  // key tiles of 64

    const size_t headoff = (size_t)b * TT * QS + (size_t)h * HD;
    const __half* Qg = QKV + headoff + (size_t)t0 * QS;

    // ---- G0: Q tile (128x64) ----
    #pragma unroll
    for (int i = 0; i < 4; i++) {
        int idx = tid + i * 256;          // 0..1023
        int r = idx >> 3, ch = idx & 7;
        uint32_t soff = (uint32_t)(r * 128 + ((ch ^ (r & 7)) << 4));
        CP16(sb + soff, Qg + (size_t)r * QS + ch * 8);
    }
    CP_COMMIT();

    auto ld_kv = [&](int slot, int kb) {
        const __half* Kg = QKV + CC   + headoff + (size_t)(kb * AK) * QS;
        const __half* Vg = QKV + 2*CC + headoff + (size_t)(kb * AK) * QS;
        uint32_t kb32 = sb + ASM_K + slot * 8192;
        uint32_t vb32 = sb + ASM_V + slot * 8192;
        #pragma unroll
        for (int i = 0; i < 2; i++) {
            int idx = tid + i * 256;      // 0..511
            int r = idx >> 3, ch = idx & 7;
            uint32_t soff = (uint32_t)(r * 128 + ((ch ^ (r & 7)) << 4));
            CP16(kb32 + soff, Kg + (size_t)r * QS + ch * 8);
            CP16(vb32 + soff, Vg + (size_t)r * QS + ch * 8);
        }
    };

    // prologue: G1=kv0, G2=kv1, G3=kv2 (guards; commit regardless)
    ld_kv(0, 0);                 CP_COMMIT();
    ld_kv(1, 1);                 CP_COMMIT();   // nkv >= 2 always
    if (nkv > 2) ld_kv(2, 2);    CP_COMMIT();

    uint32_t qf[4][4];
    float acc[8][4];
    #pragma unroll
    for (int n = 0; n < 8; n++)
        #pragma unroll
        for (int c = 0; c < 4; c++) acc[n][c] = 0.f;
    float m0 = -1e30f, m1 = -1e30f, l0 = 0.f, l1 = 0.f;
    const float cl = 0.04508422f;         // log2(e)/32

    const int g = lid >> 2;
    const int tg = lid & 3;
    const int qg0 = t0 + wid * 16 + g;    // global query row (row0)

    for (int kb = 0; kb < nkv; kb++) {
        CP_WAIT2();
        __syncthreads();   // frees KV slot (kb-1)%4

        if (kb == 0) {
            #pragma unroll
            for (int kk = 0; kk < 4; kk++) {
                int row = wid * 16 + (lid & 7) + ((lid >> 3) & 1) * 8;
                int ch  = 2 * kk + (lid >> 4);
                uint32_t addr = sb + (uint32_t)(row * 128 + ((ch ^ (row & 7)) << 4));
                LDSM4(qf[kk][0], qf[kk][1], qf[kk][2], qf[kk][3], addr);
            }
        }

        const uint32_t kbase = sb + ASM_K + (kb & 3) * 8192;
        const uint32_t vbase = sb + ASM_V + (kb & 3) * 8192;

        // ---- S = Q K^T (raw, unscaled) ----
        float s[8][4];
        #pragma unroll
        for (int j = 0; j < 8; j++)
            #pragma unroll
            for (int c = 0; c < 4; c++) s[j][c] = 0.f;

        #pragma unroll
        for (int kk = 0; kk < 4; kk++) {
            #pragma unroll
            for (int jp = 0; jp < 4; jp++) {
                int t = lid >> 3;
                int j = 2 * jp + (t >> 1);
                int ch = 2 * kk + (t & 1);
                int keyrow = 8 * j + (lid & 7);
                uint32_t addr = kbase + (uint32_t)(keyrow * 128 + ((ch ^ (keyrow & 7)) << 4));
                uint32_t f0, f1, f2, f3;
                LDSM4(f0, f1, f2, f3, addr);
                MMA16816(s[2 * jp],     qf[kk], f0, f1);
                MMA16816(s[2 * jp + 1], qf[kk], f2, f3);
            }
        }

        if (kb >= nkv - 2) {     // only last two key tiles can hit the diagonal
            #pragma unroll
            for (int j = 0; j < 8; j++) {
                int kc = kb * AK + 8 * j + tg * 2;
                if (kc     > qg0)     s[j][0] = -1e30f;
                if (kc + 1 > qg0)     s[j][1] = -1e30f;
                if (kc     > qg0 + 8) s[j][2] = -1e30f;
                if (kc + 1 > qg0 + 8) s[j][3] = -1e30f;
            }
        }

        // ---- row max ----
        float tm0 = -1e30f, tm1 = -1e30f;
        #pragma unroll
        for (int j = 0; j < 8; j++) {
            tm0 = fmaxf(tm0, fmaxf(s[j][0], s[j][1]));
            tm1 = fmaxf(tm1, fmaxf(s[j][2], s[j][3]));
        }
        tm0 = fmaxf(tm0, __shfl_xor_sync(0xffffffffu, tm0, 1));
        tm0 = fmaxf(tm0, __shfl_xor_sync(0xffffffffu, tm0, 2));
        tm1 = fmaxf(tm1, __shfl_xor_sync(0xffffffffu, tm1, 1));
        tm1 = fmaxf(tm1, __shfl_xor_sync(0xffffffffu, tm1, 2));

        float mn0 = fmaxf(m0, tm0 * cl), mn1 = fmaxf(m1, tm1 * cl);
        float cr0 = exp2f(m0 - mn0), cr1 = exp2f(m1 - mn1);
        m0 = mn0; m1 = mn1;

        // ---- P = 2^(s*cl - m) into packed fp16 fragments ----
        uint32_t ap[4][4];
        #pragma unroll
        for (int kk = 0; kk < 4; kk++) {
            ap[kk][0] = exp2_pair(fmaf(s[2*kk][0],   cl, -mn0), fmaf(s[2*kk][1],   cl, -mn0));
            ap[kk][1] = exp2_pair(fmaf(s[2*kk][2],   cl, -mn1), fmaf(s[2*kk][3],   cl, -mn1));
            ap[kk][2] = exp2_pair(fmaf(s[2*kk+1][0], cl, -mn0), fmaf(s[2*kk+1][1], cl, -mn0));
            ap[kk][3] = exp2_pair(fmaf(s[2*kk+1][2], cl, -mn1), fmaf(s[2*kk+1][3], cl, -mn1));
        }

        // ---- row sums via P @ ones ----
        float ld[4] = {0.f, 0.f, 0.f, 0.f};
        #pragma unroll
        for (int kk = 0; kk < 4; kk++)
            MMA16816(ld, ap[kk], ONES16, ONES16);
        l0 = l0 * cr0 + ld[0];
        l1 = l1 * cr1 + ld[2];

        #pragma unroll
        for (int n = 0; n < 8; n++) {
            acc[n][0] *= cr0; acc[n][1] *= cr0;
            acc[n][2] *= cr1; acc[n][3] *= cr1;
        }

        // ---- acc += P V ----
        #pragma unroll
        for (int kk = 0; kk < 4; kk++) {
            #pragma unroll
            for (int np = 0; np < 4; np++) {
                int t = lid >> 3;
                int n = 2 * np + (t >> 1);
                int keyrow = 16 * kk + (t & 1) * 8 + (lid & 7);
                uint32_t addr = vbase + (uint32_t)(keyrow * 128 + ((n ^ (keyrow & 7)) << 4));
                uint32_t f0, f1, f2, f3;
                LDSM4T(f0, f1, f2, f3, addr);
                MMA16816(acc[2 * np],     ap[kk], f0, f1);
                MMA16816(acc[2 * np + 1], ap[kk], f2, f3);
            }
        }

        if (kb + 3 < nkv) ld_kv((kb + 3) & 3, kb + 3);
        CP_COMMIT();
    }

    float inv0 = 1.f / l0, inv1 = 1.f / l1;
    const size_t yoff = (size_t)b * TT * CC + (size_t)h * HD;
    __half* Y0 = Y + yoff + (size_t)(t0 + wid * 16 + g) * CC + tg * 2;
    __half* Y1 = Y0 + 8 * CC;
    #pragma unroll
    for (int n = 0; n < 8; n++) {
        *(__half2*)(Y0 + n * 8) = __floats2half2_rn(acc[n][0] * inv0, acc[n][1] * inv0);
        *(__half2*)(Y1 + n * 8) = __floats2half2_rn(acc[n][2] * inv1, acc[n][3] * inv1);
    }
}

// ============================================================
extern "C" void kernel_launch(void* const* d_in, const int* in_sizes, int n_in,
                              void* d_out, int out_size) {
    const float* x  = (const float*)d_in[0];
    const float* Wq = (const float*)d_in[1];
    const float* bq = (const float*)d_in[2];
    const float* Wk = (const float*)d_in[3];
    const float* bk = (const float*)d_in[4];
    const float* Wv = (const float*)d_in[5];
    const float* bv = (const float*)d_in[6];
    const float* Wo = (const float*)d_in[7];
    const float* bo = (const float*)d_in[8];

    __half *x16, *w16, *qkv16, *y16;
    float *bqkv;
    cudaGetSymbolAddress((void**)&x16,   g_x16);
    cudaGetSymbolAddress((void**)&w16,   g_w16);
    cudaGetSymbolAddress((void**)&qkv16, g_qkv16);
    cudaGetSymbolAddress((void**)&y16,   g_y16);
    cudaGetSymbolAddress((void**)&bqkv,  g_bqkv);

    cudaFuncSetAttribute(gemm_mma<__half>, cudaFuncAttributeMaxDynamicSharedMemorySize, GSMEM);
    cudaFuncSetAttribute(gemm_mma<float>,  cudaFuncAttributeMaxDynamicSharedMemorySize, GSMEM);
    cudaFuncSetAttribute(attn_mma,         cudaFuncAttributeMaxDynamicSharedMemorySize, ASMEM);

    cvt_all<<<3072, 256>>>((const float4*)x, (const float4*)Wq, (const float4*)Wk,
                           (const float4*)Wv, (const float4*)Wo,
                           (__half2*)x16, (__half2*)w16);
    pack_bias<<<QS / 256, 256>>>(bq, bk, bv, bqkv);

    dim3 gqkv(QS / GBN, MT / GBM);   // (24, 64)
    gemm_mma<__half><<<gqkv, 128, GSMEM>>>(x16, w16, bqkv, qkv16, QS);

    dim3 ag(TT / AQ, BB * HH);       // (16, 64)
    attn_mma<<<ag, 256, ASMEM>>>(qkv16, y16);

    dim3 go(CC / GBN, MT / GBM);     // (8, 64)
    gemm_mma<float><<<go, 128, GSMEM>>>(y16, w16 + 3*CC*CC, bo, (float*)d_out, CC);
}

// round 13
// speedup vs baseline: 1.1575x; 1.0379x over previous
#include <cuda_runtime.h>
#include <cuda_fp16.h>
#include <math.h>
#include <stdint.h>

#define BB 4
#define TT 2048
#define CC 1024
#define HH 16
#define HD 64
#define MT (BB*TT)   // 8192
#define QS (3*CC)    // fused QKV row stride = 3072

// ---- scratch (static device arrays; no allocation allowed) ----
__device__ __half g_x16[MT*CC];
__device__ __half g_w16[4*CC*CC];     // Wq,Wk,Wv packed + Wo
__device__ float  g_bqkv[QS];
__device__ __half g_qkv16[(size_t)MT*QS];
__device__ __half g_y16[MT*CC];

// ============================================================
// PTX helpers
// ============================================================
__device__ __forceinline__ uint32_t smem_u32(const void* p) {
    uint32_t a;
    asm("{ .reg .u64 t; cvta.to.shared.u64 t, %1; cvt.u32.u64 %0, t; }" : "=r"(a) : "l"(p));
    return a;
}
#define CP16(dst, src) \
    asm volatile("cp.async.cg.shared.global [%0], [%1], 16;" :: "r"(dst), "l"(src))
#define CP_COMMIT() asm volatile("cp.async.commit_group;" ::: "memory")
#define CP_WAIT0()  asm volatile("cp.async.wait_group 0;" ::: "memory")
#define CP_WAIT1()  asm volatile("cp.async.wait_group 1;" ::: "memory")
#define CP_WAIT2()  asm volatile("cp.async.wait_group 2;" ::: "memory")
#define LDSM4(r0, r1, r2, r3, addr) \
    asm volatile("ldmatrix.sync.aligned.m8n8.x4.shared.b16 {%0,%1,%2,%3}, [%4];" \
                 : "=r"(r0), "=r"(r1), "=r"(r2), "=r"(r3) : "r"(addr))
#define LDSM4T(r0, r1, r2, r3, addr) \
    asm volatile("ldmatrix.sync.aligned.m8n8.x4.trans.shared.b16 {%0,%1,%2,%3}, [%4];" \
                 : "=r"(r0), "=r"(r1), "=r"(r2), "=r"(r3) : "r"(addr))
#define MMA16816(d, a, b0, b1) \
    asm volatile("mma.sync.aligned.m16n8k16.row.col.f32.f16.f16.f32 " \
                 "{%0,%1,%2,%3}, {%4,%5,%6,%7}, {%8,%9}, {%0,%1,%2,%3};" \
                 : "+f"((d)[0]), "+f"((d)[1]), "+f"((d)[2]), "+f"((d)[3]) \
                 : "r"((a)[0]), "r"((a)[1]), "r"((a)[2]), "r"((a)[3]), \
                   "r"(b0), "r"(b1))

// exp2 of two fp32 args -> packed fp16x2 (lo, hi)
__device__ __forceinline__ uint32_t exp2_pair(float lo, float hi) {
    uint32_t h, d;
    asm("cvt.rn.f16x2.f32 %0, %1, %2;" : "=r"(h) : "f"(hi), "f"(lo));
    asm("ex2.approx.f16x2 %0, %1;" : "=r"(d) : "r"(h));
    return d;
}

// ============================================================
// Fused fp32 -> fp16 convert: x (MT*CC) + 4 weights (CC*CC each)
// ============================================================
#define N4X (MT*CC/4)       // 2097152
#define N4W (CC*CC/4)       // 262144
#define N4TOT (N4X + 4*N4W) // 3145728

__global__ __launch_bounds__(256) void cvt_all(
    const float4* __restrict__ x,
    const float4* __restrict__ w0, const float4* __restrict__ w1,
    const float4* __restrict__ w2, const float4* __restrict__ w3,
    __half2* __restrict__ xd, __half2* __restrict__ wd)
{
    const int stride = gridDim.x * blockDim.x;
    for (int i = blockIdx.x * blockDim.x + threadIdx.x; i < N4TOT; i += stride) {
        const float4* s; __half2* d; int off;
        if (i < N4X) { s = x; d = xd; off = i; }
        else {
            int j = i - N4X;
            int rg = j >> 18;                 // N4W = 2^18
            off = j & (N4W - 1);
            s = (rg == 0) ? w0 : (rg == 1) ? w1 : (rg == 2) ? w2 : w3;
            d = wd + (size_t)rg * (2 * N4W);
        }
        float4 v = s[off];
        d[2*off]   = __floats2half2_rn(v.x, v.y);
        d[2*off+1] = __floats2half2_rn(v.z, v.w);
    }
}

__global__ void pack_bias(const float* __restrict__ bq, const float* __restrict__ bk,
                          const float* __restrict__ bv, float* __restrict__ o)
{
    int i = blockIdx.x * blockDim.x + threadIdx.x;   // 0..3071
    const float* src = (i < CC) ? bq : (i < 2*CC) ? bk : bv;
    o[i] = src[i & (CC - 1)];
}

// ============================================================
// HMMA GEMM: Y[m,n] = sum_k A[m,k]*B[n,k] + bias[n]
// BM=128 BN=128 BK=64, 4 warps (2x2), warp tile 64x64, m16n8k16.
// 3-stage cp.async ring (32KB/stage), ONE barrier per iteration,
// wait_group 1, 2 CTAs/SM. Swizzle c^(r&7) on 128B rows.
// ============================================================
#define GBM 128
#define GBN 128
#define GBK 64
#define NKIT (CC/GBK)        // 16
#define A_B 16384            // 128x64 fp16
#define B_B 16384
#define STG_B (A_B + B_B)    // 32768
#define NSTG 3
#define GSMEM (NSTG*STG_B)   // 98304

__device__ __forceinline__ void ld_stage(
    uint32_t sbase, int stage,
    const __half* __restrict__ A, const __half* __restrict__ B,
    int m0, int n0, int k0, int tid)
{
    uint32_t st = sbase + stage * STG_B;
    #pragma unroll
    for (int t = 0; t < 8; t++) {        // 1024 16B chunks each for A and B
        int i = tid + t * 128;
        int r = i >> 3, c = i & 7;
        uint32_t soff = ((uint32_t)(r * 8 + (c ^ (r & 7)))) << 4;
        CP16(st + soff,       A + (size_t)(m0 + r) * CC + k0 + c * 8);
        CP16(st + A_B + soff, B + (size_t)(n0 + r) * CC + k0 + c * 8);
    }
}

template <typename OutT>
__global__ __launch_bounds__(128, 2) void gemm_mma(
    const __half* __restrict__ A, const __half* __restrict__ B,
    const float* __restrict__ bias, OutT* __restrict__ Y, int ldc)
{
    extern __shared__ char smem[];
    const uint32_t sbase = smem_u32(smem);
    const int tid = threadIdx.x, wid = tid >> 5, lid = tid & 31;
    const int m0 = blockIdx.y * GBM, n0 = blockIdx.x * GBN;
    const int wm = wid >> 1, wn = wid & 1;     // 2x2 warp grid, tile 64x64

    float acc[4][8][4];
    #pragma unroll
    for (int a = 0; a < 4; a++)
        #pragma unroll
        for (int b = 0; b < 8; b++)
            #pragma unroll
            for (int c = 0; c < 4; c++) acc[a][b][c] = 0.f;

    // prologue: stages 0,1 -> groups G0,G1
    ld_stage(sbase, 0, A, B, m0, n0, 0, tid);   CP_COMMIT();
    ld_stage(sbase, 1, A, B, m0, n0, GBK, tid); CP_COMMIT();

    const int a_r = wm * 64 + (lid & 15);
    const int a_c = lid >> 4;
    const int b_r = wn * 64 + (lid & 7) + ((lid >> 4) << 3);
    const int b_c = (lid & 15) >> 3;

    for (int kb = 0; kb < NKIT; kb++) {
        CP_WAIT1();
        __syncthreads();   // frees slot (kb-1)%3 (consumed last iter)
        const uint32_t st = sbase + (kb % 3) * STG_B;

        #pragma unroll
        for (int kk = 0; kk < 4; kk++) {
            uint32_t af[4][4], bf[4][4];
            #pragma unroll
            for (int mi = 0; mi < 4; mi++) {
                int r = a_r + mi * 16;
                int c16 = kk * 2 + a_c;
                uint32_t off = ((uint32_t)(r * 8 + (c16 ^ (r & 7)))) << 4;
                LDSM4(af[mi][0], af[mi][1], af[mi][2], af[mi][3], st + off);
            }
            #pragma unroll
            for (int nj = 0; nj < 4; nj++) {
                int r = b_r + nj * 16;
                int c16 = kk * 2 + b_c;
                uint32_t off = ((uint32_t)(r * 8 + (c16 ^ (r & 7)))) << 4;
                LDSM4(bf[nj][0], bf[nj][1], bf[nj][2], bf[nj][3], st + A_B + off);
            }
            #pragma unroll
            for (int mi = 0; mi < 4; mi++)
                #pragma unroll
                for (int nj = 0; nj < 4; nj++) {
                    MMA16816(acc[mi][nj * 2],     af[mi], bf[nj][0], bf[nj][1]);
                    MMA16816(acc[mi][nj * 2 + 1], af[mi], bf[nj][2], bf[nj][3]);
                }
        }
        if (kb + 2 < NKIT)
            ld_stage(sbase, (kb + 2) % 3, A, B, m0, n0, (kb + 2) * GBK, tid);
        CP_COMMIT();
    }

    #pragma unroll
    for (int mi = 0; mi < 4; mi++) {
        #pragma unroll
        for (int nj = 0; nj < 8; nj++) {
            int row = m0 + wm * 64 + mi * 16 + (lid >> 2);
            int col = n0 + wn * 64 + nj * 8 + (lid & 3) * 2;
            float b0 = __ldg(bias + col), b1 = __ldg(bias + col + 1);
            float v00 = acc[mi][nj][0] + b0, v01 = acc[mi][nj][1] + b1;
            float v10 = acc[mi][nj][2] + b0, v11 = acc[mi][nj][3] + b1;
            if (sizeof(OutT) == 2) {
                *(__half2*)((__half*)Y + (size_t)row * ldc + col)       = __floats2half2_rn(v00, v01);
                *(__half2*)((__half*)Y + (size_t)(row + 8) * ldc + col) = __floats2half2_rn(v10, v11);
            } else {
                *(float2*)((float*)Y + (size_t)row * ldc + col)       = make_float2(v00, v01);
                *(float2*)((float*)Y + (size_t)(row + 8) * ldc + col) = make_float2(v10, v11);
            }
        }
    }
}

// ============================================================
// Flash attention (causal), m16n8k16 fp16 HMMA, base-2 softmax.
// AQ=64 queries/CTA, 4 warps x 16 rows, AK=64 keys/tile, full keys
// per warp (no key-split). 3-slot K and V cp.async rings, one barrier
// per tile, wait_group 1. smem: Q [0,8K) | K [8K,32K) | V [32K,56K).
// 56KB + 128 regs -> 4 CTAs/SM (occ 50%).
// ============================================================
#define AQ 64
#define AK 64
#define ONES16 0x3C003C00u
#define ASM_K 8192
#define ASM_V 32768
#define ASMEM 57344

__global__ __launch_bounds__(128, 4) void attn_mma(
    const __half* __restrict__ QKV, __half* __restrict__ Y)
{
    extern __shared__ char sm[];
    const uint32_t sb = smem_u32(sm);

    const int tid = threadIdx.x, wid = tid >> 5, lid = tid & 31;
    const int bh = blockIdx.y;
    const int b  = bh / HH;
    const int h  = bh % HH;
    const int qt = gridDim.x - 1 - blockIdx.x;   // long blocks first
    const int t0 = qt * AQ;
    const int nkv = qt + 1;                      // 64-key tiles

    const size_t headoff = (size_t)b * TT * QS + (size_t)h * HD;
    const __half* Qg = QKV + headoff + (size_t)t0 * QS;

    // ---- G0: Q tile (64x64) ----
    #pragma unroll
    for (int i = 0; i < 4; i++) {
        int idx = tid + i * 128;          // 0..511
        int r = idx >> 3, ch = idx & 7;
        uint32_t soff = (uint32_t)(r * 128 + ((ch ^ (r & 7)) << 4));
        CP16(sb + soff, Qg + (size_t)r * QS + ch * 8);
    }
    CP_COMMIT();

    auto ld_kv = [&](int slot, int kb) {
        const __half* Kg = QKV + CC   + headoff + (size_t)(kb * AK) * QS;
        const __half* Vg = QKV + 2*CC + headoff + (size_t)(kb * AK) * QS;
        uint32_t kb32 = sb + ASM_K + slot * 8192;
        uint32_t vb32 = sb + ASM_V + slot * 8192;
        #pragma unroll
        for (int i = 0; i < 4; i++) {
            int idx = tid + i * 128;      // 0..511
            int r = idx >> 3, ch = idx & 7;
            uint32_t soff = (uint32_t)(r * 128 + ((ch ^ (r & 7)) << 4));
            CP16(kb32 + soff, Kg + (size_t)r * QS + ch * 8);
            CP16(vb32 + soff, Vg + (size_t)r * QS + ch * 8);
        }
    };

    // prologue: G1=kv0, G2=kv1 (guard; commit regardless)
    ld_kv(0, 0);                 CP_COMMIT();
    if (nkv > 1) ld_kv(1, 1);    CP_COMMIT();

    uint32_t qf[4][4];
    float acc[8][4];
    #pragma unroll
    for (int n = 0; n < 8; n++)
        #pragma unroll
        for (int c = 0; c < 4; c++) acc[n][c] = 0.f;
    float m0 = -1e30f, m1 = -1e30f, l0 = 0.f, l1 = 0.f;
    const float cl = 0.04508422f;         // log2(e)/32

    const int g = lid >> 2;
    const int tg = lid & 3;
    const int qg0 = t0 + wid * 16 + g;    // global query row (row0)

    for (int kb = 0; kb < nkv; kb++) {
        // need kv_kb (group kb+1); at most 1 newer group pending -> wait 1
        CP_WAIT1();
        __syncthreads();   // frees KV slot (kb-1)%3

        if (kb == 0) {
            #pragma unroll
            for (int kk = 0; kk < 4; kk++) {
                int row = wid * 16 + (lid & 7) + ((lid >> 3) & 1) * 8;
                int ch  = 2 * kk + (lid >> 4);
                uint32_t addr = sb + (uint32_t)(row * 128 + ((ch ^ (row & 7)) << 4));
                LDSM4(qf[kk][0], qf[kk][1], qf[kk][2], qf[kk][3], addr);
            }
        }

        const uint32_t kbase = sb + ASM_K + (kb % 3) * 8192;
        const uint32_t vbase = sb + ASM_V + (kb % 3) * 8192;

        // ---- S = Q K^T (raw, unscaled) ----
        float s[8][4];
        #pragma unroll
        for (int j = 0; j < 8; j++)
            #pragma unroll
            for (int c = 0; c < 4; c++) s[j][c] = 0.f;

        #pragma unroll
        for (int kk = 0; kk < 4; kk++) {
            #pragma unroll
            for (int jp = 0; jp < 4; jp++) {
                int t = lid >> 3;
                int j = 2 * jp + (t >> 1);
                int ch = 2 * kk + (t & 1);
                int keyrow = 8 * j + (lid & 7);
                uint32_t addr = kbase + (uint32_t)(keyrow * 128 + ((ch ^ (keyrow & 7)) << 4));
                uint32_t f0, f1, f2, f3;
                LDSM4(f0, f1, f2, f3, addr);
                MMA16816(s[2 * jp],     qf[kk], f0, f1);
                MMA16816(s[2 * jp + 1], qf[kk], f2, f3);
            }
        }

        if (kb == nkv - 1) {     // AQ==AK: only diagonal tile needs mask
            #pragma unroll
            for (int j = 0; j < 8; j++) {
                int kc = kb * AK + 8 * j + tg * 2;
                if (kc     > qg0)     s[j][0] = -1e30f;
                if (kc + 1 > qg0)     s[j][1] = -1e30f;
                if (kc     > qg0 + 8) s[j][2] = -1e30f;
                if (kc + 1 > qg0 + 8) s[j][3] = -1e30f;
            }
        }

        // ---- row max ----
        float tm0 = -1e30f, tm1 = -1e30f;
        #pragma unroll
        for (int j = 0; j < 8; j++) {
            tm0 = fmaxf(tm0, fmaxf(s[j][0], s[j][1]));
            tm1 = fmaxf(tm1, fmaxf(s[j][2], s[j][3]));
        }
        tm0 = fmaxf(tm0, __shfl_xor_sync(0xffffffffu, tm0, 1));
        tm0 = fmaxf(tm0, __shfl_xor_sync(0xffffffffu, tm0, 2));
        tm1 = fmaxf(tm1, __shfl_xor_sync(0xffffffffu, tm1, 1));
        tm1 = fmaxf(tm1, __shfl_xor_sync(0xffffffffu, tm1, 2));

        float mn0 = fmaxf(m0, tm0 * cl), mn1 = fmaxf(m1, tm1 * cl);
        float cr0 = exp2f(m0 - mn0), cr1 = exp2f(m1 - mn1);
        m0 = mn0; m1 = mn1;

        // ---- P = 2^(s*cl - m) into packed fp16 fragments ----
        uint32_t ap[4][4];
        #pragma unroll
        for (int kk = 0; kk < 4; kk++) {
            ap[kk][0] = exp2_pair(fmaf(s[2*kk][0],   cl, -mn0), fmaf(s[2*kk][1],   cl, -mn0));
            ap[kk][1] = exp2_pair(fmaf(s[2*kk][2],   cl, -mn1), fmaf(s[2*kk][3],   cl, -mn1));
            ap[kk][2] = exp2_pair(fmaf(s[2*kk+1][0], cl, -mn0), fmaf(s[2*kk+1][1], cl, -mn0));
            ap[kk][3] = exp2_pair(fmaf(s[2*kk+1][2], cl, -mn1), fmaf(s[2*kk+1][3], cl, -mn1));
        }

        // ---- row sums via P @ ones ----
        float ld[4] = {0.f, 0.f, 0.f, 0.f};
        #pragma unroll
        for (int kk = 0; kk < 4; kk++)
            MMA16816(ld, ap[kk], ONES16, ONES16);
        l0 = l0 * cr0 + ld[0];
        l1 = l1 * cr1 + ld[2];

        #pragma unroll
        for (int n = 0; n < 8; n++) {
            acc[n][0] *= cr0; acc[n][1] *= cr0;
            acc[n][2] *= cr1; acc[n][3] *= cr1;
        }

        // ---- acc += P V ----
        #pragma unroll
        for (int kk = 0; kk < 4; kk++) {
            #pragma unroll
            for (int np = 0; np < 4; np++) {
                int t = lid >> 3;
                int n = 2 * np + (t >> 1);
                int keyrow = 16 * kk + (t & 1) * 8 + (lid & 7);
                uint32_t addr = vbase + (uint32_t)(keyrow * 128 + ((n ^ (keyrow & 7)) << 4));
                uint32_t f0, f1, f2, f3;
                LDSM4T(f0, f1, f2, f3, addr);
                MMA16816(acc[2 * np],     ap[kk], f0, f1);
                MMA16816(acc[2 * np + 1], ap[kk], f2, f3);
            }
        }

        // prefetch kv_{kb+2} into slot (kb+2)%3 == (kb-1)%3
        if (kb + 2 < nkv) ld_kv((kb + 2) % 3, kb + 2);
        CP_COMMIT();
    }

    float inv0 = 1.f / l0, inv1 = 1.f / l1;
    const size_t yoff = (size_t)b * TT * CC + (size_t)h * HD;
    __half* Y0 = Y + yoff + (size_t)(t0 + wid * 16 + g) * CC + tg * 2;
    __half* Y1 = Y0 + 8 * CC;
    #pragma unroll
    for (int n = 0; n < 8; n++) {
        *(__half2*)(Y0 + n * 8) = __floats2half2_rn(acc[n][0] * inv0, acc[n][1] * inv0);
        *(__half2*)(Y1 + n * 8) = __floats2half2_rn(acc[n][2] * inv1, acc[n][3] * inv1);
    }
}

// ============================================================
extern "C" void kernel_launch(void* const* d_in, const int* in_sizes, int n_in,
                              void* d_out, int out_size) {
    const float* x  = (const float*)d_in[0];
    const float* Wq = (const float*)d_in[1];
    const float* bq = (const float*)d_in[2];
    const float* Wk = (const float*)d_in[3];
    const float* bk = (const float*)d_in[4];
    const float* Wv = (const float*)d_in[5];
    const float* bv = (const float*)d_in[6];
    const float* Wo = (const float*)d_in[7];
    const float* bo = (const float*)d_in[8];

    __half *x16, *w16, *qkv16, *y16;
    float *bqkv;
    cudaGetSymbolAddress((void**)&x16,   g_x16);
    cudaGetSymbolAddress((void**)&w16,   g_w16);
    cudaGetSymbolAddress((void**)&qkv16, g_qkv16);
    cudaGetSymbolAddress((void**)&y16,   g_y16);
    cudaGetSymbolAddress((void**)&bqkv,  g_bqkv);

    cudaFuncSetAttribute(gemm_mma<__half>, cudaFuncAttributeMaxDynamicSharedMemorySize, GSMEM);
    cudaFuncSetAttribute(gemm_mma<float>,  cudaFuncAttributeMaxDynamicSharedMemorySize, GSMEM);
    cudaFuncSetAttribute(attn_mma,         cudaFuncAttributeMaxDynamicSharedMemorySize, ASMEM);

    cvt_all<<<3072, 256>>>((const float4*)x, (const float4*)Wq, (const float4*)Wk,
                           (const float4*)Wv, (const float4*)Wo,
                           (__half2*)x16, (__half2*)w16);
    pack_bias<<<QS / 256, 256>>>(bq, bk, bv, bqkv);

    dim3 gqkv(QS / GBN, MT / GBM);   // (24, 64)
    gemm_mma<__half><<<gqkv, 128, GSMEM>>>(x16, w16, bqkv, qkv16, QS);

    dim3 ag(TT / AQ, BB * HH);       // (32, 64)
    attn_mma<<<ag, 128, ASMEM>>>(qkv16, y16);

    dim3 go(CC / GBN, MT / GBM);     // (8, 64)
    gemm_mma<float><<<go, 128, GSMEM>>>(y16, w16 + 3*CC*CC, bo, (float*)d_out, CC);
}